// round 13
// baseline (speedup 1.0000x reference)
#include <cuda_runtime.h>
#include <math.h>
#include <stdint.h>

#define SLEN  2048
#define DIMC  1024
#define NH    16
#define HDIM  64
#define BATCH 2
#define MROWS (BATCH*SLEN)   /* 4096 */
#define IOS   1008           /* DIM - 16 */

// ---- scratch (allocation-free rule: __device__ globals) ----
__device__ float g_q [(size_t)MROWS * DIMC];
__device__ float g_k [(size_t)MROWS * DIMC];
__device__ float g_v [(size_t)MROWS * DIMC];
__device__ float g_ao[(size_t)MROWS * DIMC];
__device__ float g_wt[(size_t)4 * DIMC * DIMC];   // transposed weights

__device__ __forceinline__ uint32_t f2tf(float f) {
    uint32_t u;
    asm("cvt.rna.tf32.f32 %0, %1;" : "=r"(u) : "f"(f));
    return u;
}

// D = A(16x8 tf32, row) * B(8x8 tf32, col) + D (fp32). fp32 operands truncate (RZ).
__device__ __forceinline__ void mma8(float c[4], const uint32_t a[4], const uint32_t b[2]) {
    asm volatile(
        "mma.sync.aligned.m16n8k8.row.col.f32.tf32.tf32.f32 "
        "{%0,%1,%2,%3}, {%4,%5,%6,%7}, {%8,%9}, {%0,%1,%2,%3};"
        : "+f"(c[0]), "+f"(c[1]), "+f"(c[2]), "+f"(c[3])
        : "r"(a[0]), "r"(a[1]), "r"(a[2]), "r"(a[3]), "r"(b[0]), "r"(b[1]));
}

__device__ __forceinline__ void ldsm4(uint32_t r[4], uint32_t saddr) {
    asm volatile("ldmatrix.sync.aligned.m8n8.x4.shared.b16 {%0,%1,%2,%3}, [%4];"
        : "=r"(r[0]), "=r"(r[1]), "=r"(r[2]), "=r"(r[3]) : "r"(saddr));
}

__device__ __forceinline__ void cpa16(uint32_t saddr, const void* gp) {
    asm volatile("cp.async.cg.shared.global [%0], [%1], 16;" :: "r"(saddr), "l"(gp));
}
__device__ __forceinline__ void cp_commit() {
    asm volatile("cp.async.commit_group;" ::: "memory");
}
template<int N> __device__ __forceinline__ void cp_wait() {
    asm volatile("cp.async.wait_group %0;" :: "n"(N) : "memory");
}

// ============================================================
// Weight transpose: g_wt[z] = W_z^T (k-contiguous rows).
// ============================================================
__global__ __launch_bounds__(256) void transpose_w(
    const float* __restrict__ w0, const float* __restrict__ w1,
    const float* __restrict__ w2, const float* __restrict__ w3,
    float* __restrict__ wt)
{
    __shared__ float t[32][33];
    const float* W = (blockIdx.z == 0) ? w0 : (blockIdx.z == 1) ? w1
                   : (blockIdx.z == 2) ? w2 : w3;
    float* WT = wt + (size_t)blockIdx.z * DIMC * DIMC;
    const int x0 = blockIdx.x * 32, y0 = blockIdx.y * 32;
    #pragma unroll
    for (int i = threadIdx.y; i < 32; i += 8)
        t[i][threadIdx.x] = W[(size_t)(y0 + i) * DIMC + x0 + threadIdx.x];
    __syncthreads();
    #pragma unroll
    for (int i = threadIdx.y; i < 32; i += 8)
        WT[(size_t)(x0 + i) * DIMC + y0 + threadIdx.x] = t[threadIdx.x][i];
}

// ============================================================
// tf32 GEMM (NT): C = A @ BT^T, both operands k-contiguous.
// 128x128 block tile, 8 warps, warp 64x32, K-step 16,
// 4-stage cp.async pipeline (3 tiles in flight), ldmatrix frags.
// ============================================================
#define GS 20              /* smem row stride (words); 20r mod 32 spans all banks */
#define TSTG (128 * GS)    /* words per operand tile stage */
#define GSTG 4
#define GEMM_SMEM (2 * GSTG * TSTG * 4)   /* A + B stages = 81920... (2*4*2560*4) */

__device__ __forceinline__ void gemm_body(
    const float* __restrict__ A, const float* __restrict__ BT,
    float* __restrict__ C, const float* __restrict__ resid,
    const float* __restrict__ getc, const float* __restrict__ putc,
    bool cvt, float scale)
{
    extern __shared__ uint32_t smem[];
    uint32_t* sA = smem;                 // GSTG stages
    uint32_t* sB = smem + GSTG * TSTG;   // GSTG stages

    const int tid = threadIdx.x, lane = tid & 31, w = tid >> 5;
    const int g = lane >> 2, tg = lane & 3;
    const int wm = w >> 2, wn = w & 3;
    const int m0 = blockIdx.y * 128, n0 = blockIdx.x * 128;

    const int r0 = tid >> 2, kc = (tid & 3) * 4;

    const uint32_t sAa = (uint32_t)__cvta_generic_to_shared(sA);
    const uint32_t sBa = (uint32_t)__cvta_generic_to_shared(sB);

    const float* Ap0 = &A [(size_t)(m0 + r0) * DIMC + kc];
    const float* Ap1 = Ap0 + (size_t)64 * DIMC;
    const float* Bp0 = &BT[(size_t)(n0 + r0) * DIMC + kc];
    const float* Bp1 = Bp0 + (size_t)64 * DIMC;
    const uint32_t dA0 = sAa + (r0 * GS + kc) * 4;
    const uint32_t dA1 = sAa + ((r0 + 64) * GS + kc) * 4;
    const uint32_t dB0 = sBa + (r0 * GS + kc) * 4;
    const uint32_t dB1 = sBa + ((r0 + 64) * GS + kc) * 4;

    // per-lane ldmatrix address components
    const uint32_t aLane = ((wm * 64 + (lane & 15)) * GS + ((lane >> 4) & 1) * 4) * 4;
    const uint32_t bLane = ((wn * 32 + (lane & 7) + ((lane >> 4) & 1) * 8) * GS
                            + ((lane >> 3) & 1) * 4) * 4;

    float acc[16][4];
    #pragma unroll
    for (int i = 0; i < 16; i++)
        #pragma unroll
        for (int j = 0; j < 4; j++) acc[i][j] = 0.f;

    #pragma unroll
    for (int s = 0; s < GSTG - 1; s++) {
        const int k0 = s * 16;
        cpa16(dA0 + s * TSTG * 4, Ap0 + k0);
        cpa16(dA1 + s * TSTG * 4, Ap1 + k0);
        cpa16(dB0 + s * TSTG * 4, Bp0 + k0);
        cpa16(dB1 + s * TSTG * 4, Bp1 + k0);
        cp_commit();
    }

    const int KT = DIMC / 16;
    for (int kt = 0; kt < KT; kt++) {
        cp_wait<GSTG - 2>();     // oldest (kt) done; GSTG-2 tiles still in flight
        __syncthreads();
        if (kt + GSTG - 1 < KT) {
            const int s = (kt + GSTG - 1) % GSTG;
            const int k0 = (kt + GSTG - 1) * 16;
            cpa16(dA0 + s * TSTG * 4, Ap0 + k0);
            cpa16(dA1 + s * TSTG * 4, Ap1 + k0);
            cpa16(dB0 + s * TSTG * 4, Bp0 + k0);
            cpa16(dB1 + s * TSTG * 4, Bp1 + k0);
        }
        cp_commit();

        const uint32_t aBase = sAa + (kt % GSTG) * TSTG * 4 + aLane;
        const uint32_t bBase = sBa + (kt % GSTG) * TSTG * 4 + bLane;
        #pragma unroll
        for (int ks = 0; ks < 16; ks += 8) {
            uint32_t af[4][4], bf[2][4];
            #pragma unroll
            for (int ma = 0; ma < 4; ma++)
                ldsm4(af[ma], aBase + (ma * 16 * GS + ks) * 4);
            #pragma unroll
            for (int n2 = 0; n2 < 2; n2++)
                ldsm4(bf[n2], bBase + (n2 * 16 * GS + ks) * 4);
            #pragma unroll
            for (int ma = 0; ma < 4; ma++)
                #pragma unroll
                for (int na = 0; na < 4; na++)
                    mma8(acc[ma * 4 + na], af[ma], &bf[na >> 1][(na & 1) * 2]);
        }
    }

    #pragma unroll
    for (int ma = 0; ma < 4; ma++) {
        #pragma unroll
        for (int na = 0; na < 4; na++) {
            const int rbase = m0 + wm * 64 + ma * 16 + g;
            const int cbase = n0 + wn * 32 + na * 8 + 2 * tg;
            #pragma unroll
            for (int half = 0; half < 2; half++) {
                const int m = rbase + 8 * half;
                float v0 = acc[ma * 4 + na][2 * half + 0];
                float v1 = acc[ma * 4 + na][2 * half + 1];
                if (cvt) {
                    v0 = __uint_as_float(f2tf(v0 * scale));
                    v1 = __uint_as_float(f2tf(v1 * scale));
                } else if (resid) {
                    v0 += resid[(size_t)m * DIMC + cbase];
                    v1 += resid[(size_t)m * DIMC + cbase + 1];
                    #pragma unroll
                    for (int c = 0; c < 2; c++) {
                        const int n = cbase + c;
                        float* pv = c ? &v1 : &v0;
                        if (n == IOS + 1)  *pv += getc[m];
                        if (n == IOS + 3)  *pv += putc[m];
                        if (n == IOS + 13) *pv  = putc[m];
                    }
                }
                *(float2*)&C[(size_t)m * DIMC + cbase] = make_float2(v0, v1);
            }
        }
    }
}

__global__ __launch_bounds__(256, 2) void gemm_qkv3(
    const float* __restrict__ x, const float* __restrict__ wt,
    float* __restrict__ q, float* __restrict__ k, float* __restrict__ v)
{
    const int z = blockIdx.z;
    const float* BT = wt + (size_t)z * DIMC * DIMC;
    float* C = (z == 0) ? q : (z == 1) ? k : v;
    const float scale = (z == 0) ? 0.125f : 1.0f;
    gemm_body(x, BT, C, nullptr, nullptr, nullptr, true, scale);
}

__global__ __launch_bounds__(256, 2) void gemm_out(
    const float* __restrict__ A, const float* __restrict__ wt,
    float* __restrict__ C, const float* __restrict__ resid,
    const float* __restrict__ getc, const float* __restrict__ putc)
{
    gemm_body(A, wt + (size_t)3 * DIMC * DIMC, C, resid, getc, putc, false, 1.0f);
}

// ============================================================
// Flash attention, tf32 mma, pipelined; ldmatrix for K (GEMM1 B)
// and P (GEMM2 A) fragments. 128 thr / 4 warps, warp = 16 q-rows.
// (unchanged from R10)
// ============================================================
#define AS 68
#define ATTN_SMEM (4 * 64 * AS * 4)   /* sK[2] + sV + sQP */

__global__ __launch_bounds__(128, 3) void attn_mma(
    const float* __restrict__ q, const float* __restrict__ k,
    const float* __restrict__ v, const float* __restrict__ x,
    const float* __restrict__ getc, float* __restrict__ ao)
{
    extern __shared__ uint32_t smem[];
    uint32_t* sK  = smem;               // 2 buffers
    uint32_t* sV  = sK + 2 * 64 * AS;
    uint32_t* sQP = sV + 64 * AS;

    const uint32_t sKa  = (uint32_t)__cvta_generic_to_shared(sK);
    const uint32_t sVa  = (uint32_t)__cvta_generic_to_shared(sV);
    const uint32_t sQPa = (uint32_t)__cvta_generic_to_shared(sQP);

    const int tid = threadIdx.x, lane = tid & 31, w = tid >> 5;
    const int g = lane >> 2, tg = lane & 3;
    const int it = gridDim.x - 1 - blockIdx.x;   // heavy blocks first
    const int h = blockIdx.y, b = blockIdx.z;
    const int i0 = it * 64;
    const size_t bS = (size_t)b * SLEN;

    const uint32_t kLane = (((lane & 7) + ((lane >> 4) & 1) * 8) * AS
                            + ((lane >> 3) & 1) * 4) * 4;
    const uint32_t pLane = ((w * 16 + (lane & 15)) * AS + ((lane >> 4) & 1) * 4) * 4;

    int lrow[8], lcol[8];
    #pragma unroll
    for (int i = 0; i < 8; i++) {
        const int id = tid + 128 * i;
        lrow[i] = id >> 4; lcol[i] = (id & 15) * 4;
    }

    // stage Q tile (tf32-rounded, pre-scaled) and hoist fragments
    #pragma unroll
    for (int i = 0; i < 8; i++)
        cpa16(sQPa + (lrow[i] * AS + lcol[i]) * 4,
              &q[(bS + i0 + lrow[i]) * DIMC + h * HDIM + lcol[i]]);
    cp_commit(); cp_wait<0>();
    __syncthreads();
    uint32_t afq[8][4];
    #pragma unroll
    for (int k8 = 0; k8 < 8; k8++)
        ldsm4(afq[k8], sQPa + pLane + k8 * 8 * 4);
    __syncthreads();   // sQP now free for P

    const float slope = exp2f(-0.5f * (float)(h + 1));
    const bool h0 = (h == 0);

    float m2[2] = {-INFINITY, -INFINITY}, l2[2] = {0.f, 0.f};
    float O[8][4];
    #pragma unroll
    for (int na = 0; na < 8; na++)
        #pragma unroll
        for (int j = 0; j < 4; j++) O[na][j] = 0.f;

    bool gcf[2]; float tgt[2];
    #pragma unroll
    for (int rs = 0; rs < 2; rs++) {
        const int gi = i0 + w * 16 + g + 8 * rs;
        gcf[rs] = (getc[bS + gi] > 0.5f) && h0;
        const float* xr = &x[(bS + gi) * DIMC + IOS];
        tgt[rs] = xr[0] + 1.0f + xr[1];
    }

    const int njt = h0 ? (SLEN / 64) : (it + 1);

    // prologue: K[0] -> sK buf 0
    #pragma unroll
    for (int i = 0; i < 8; i++)
        cpa16(sKa + (lrow[i] * AS + lcol[i]) * 4,
              &k[(bS + lrow[i]) * DIMC + h * HDIM + lcol[i]]);
    cp_commit();

    for (int jt = 0; jt < njt; jt++) {
        const int j0 = jt * 64;
        const int buf = jt & 1;
        __syncthreads();

        // V[jt] load overlaps GEMM1
        #pragma unroll
        for (int i = 0; i < 8; i++)
            cpa16(sVa + (lrow[i] * AS + lcol[i]) * 4,
                  &v[(bS + j0 + lrow[i]) * DIMC + h * HDIM + lcol[i]]);
        cp_commit();
        cp_wait<1>();
        __syncthreads();

        // GEMM1: S = Q @ K^T (K frags via ldmatrix)
        const uint32_t kBase = sKa + buf * 64 * AS * 4 + kLane;
        float s[8][4];
        #pragma unroll
        for (int na = 0; na < 8; na++)
            #pragma unroll
            for (int j = 0; j < 4; j++) s[na][j] = 0.f;
        #pragma unroll
        for (int k8 = 0; k8 < 8; k8++) {
            uint32_t bf[4][4];
            #pragma unroll
            for (int n2 = 0; n2 < 4; n2++)
                ldsm4(bf[n2], kBase + (n2 * 16 * AS + k8 * 8) * 4);
            #pragma unroll
            for (int na = 0; na < 8; na++)
                mma8(s[na], afq[k8], &bf[na >> 1][(na & 1) * 2]);
        }

        // prefetch next K during softmax + GEMM2
        if (jt + 1 < njt) {
            const int nj0 = (jt + 1) * 64;
            const uint32_t kb = sKa + (buf ^ 1) * 64 * AS * 4;
            #pragma unroll
            for (int i = 0; i < 8; i++)
                cpa16(kb + (lrow[i] * AS + lcol[i]) * 4,
                      &k[(bS + nj0 + lrow[i]) * DIMC + h * HDIM + lcol[i]]);
        }
        cp_commit();

        // bias + online softmax per row-half
        #pragma unroll
        for (int rs = 0; rs < 2; rs++) {
            const int gi = i0 + w * 16 + g + 8 * rs;
            if (gcf[rs]) {
                #pragma unroll
                for (int na = 0; na < 8; na++)
                    #pragma unroll
                    for (int c = 0; c < 2; c++) {
                        const int gj = j0 + na * 8 + 2 * tg + c;
                        s[na][2 * rs + c] = -slope * fabsf(tgt[rs] - (float)gj);
                    }
            } else {
                #pragma unroll
                for (int na = 0; na < 8; na++)
                    #pragma unroll
                    for (int c = 0; c < 2; c++) {
                        const int gj = j0 + na * 8 + 2 * tg + c;
                        s[na][2 * rs + c] = (gj <= gi)
                            ? s[na][2 * rs + c] - slope * (float)(gi - gj) : -1e30f;
                    }
            }
            float tm = -INFINITY;
            #pragma unroll
            for (int na = 0; na < 8; na++)
                tm = fmaxf(tm, fmaxf(s[na][2 * rs], s[na][2 * rs + 1]));
            tm = fmaxf(tm, __shfl_xor_sync(0xffffffffu, tm, 1));
            tm = fmaxf(tm, __shfl_xor_sync(0xffffffffu, tm, 2));
            const float mn = fmaxf(m2[rs], tm);
            const float alpha = __expf(m2[rs] - mn);
            m2[rs] = mn;
            float rsum = 0.f;
            #pragma unroll
            for (int na = 0; na < 8; na++)
                #pragma unroll
                for (int c = 0; c < 2; c++) {
                    float e = __expf(s[na][2 * rs + c] - mn);
                    s[na][2 * rs + c] = e; rsum += e;
                }
            rsum += __shfl_xor_sync(0xffffffffu, rsum, 1);
            rsum += __shfl_xor_sync(0xffffffffu, rsum, 2);
            l2[rs] = l2[rs] * alpha + rsum;
            #pragma unroll
            for (int na = 0; na < 8; na++) {
                O[na][2 * rs + 0] *= alpha;
                O[na][2 * rs + 1] *= alpha;
            }
        }

        cp_wait<1>();       // V_jt done (K_next may pend)
        __syncthreads();

        // P -> sP (warp-private rows), raw fp32 bits (mma truncates)
        #pragma unroll
        for (int na = 0; na < 8; na++) {
            const int r = w * 16 + g, c = na * 8 + 2 * tg;
            sQP[r * AS + c]           = __float_as_uint(s[na][0]);
            sQP[r * AS + c + 1]       = __float_as_uint(s[na][1]);
            sQP[(r + 8) * AS + c]     = __float_as_uint(s[na][2]);
            sQP[(r + 8) * AS + c + 1] = __float_as_uint(s[na][3]);
        }
        __syncwarp();

        // GEMM2: O += P @ V (P frags via ldmatrix; V row-major scalar B)
        #pragma unroll
        for (int k8 = 0; k8 < 8; k8++) {
            uint32_t af[4];
            ldsm4(af, sQPa + pLane + k8 * 8 * 4);
            #pragma unroll
            for (int na = 0; na < 8; na++) {
                uint32_t bf[2];
                const int nb = (k8 * 8 + tg) * AS + na * 8 + g;
                bf[0] = sV[nb]; bf[1] = sV[nb + 4 * AS];
                mma8(O[na], af, bf);
            }
        }
    }

    #pragma unroll
    for (int rs = 0; rs < 2; rs++) {
        const float inv = 1.0f / l2[rs];
        const size_t rowoff = (bS + i0 + w * 16 + g + 8 * rs) * DIMC + h * HDIM;
        #pragma unroll
        for (int na = 0; na < 8; na++) {
            *(float2*)&ao[rowoff + na * 8 + 2 * tg] =
                make_float2(O[na][2 * rs] * inv, O[na][2 * rs + 1] * inv);
        }
    }
}

// ============================================================
extern "C" void kernel_launch(void* const* d_in, const int* in_sizes, int n_in,
                              void* d_out, int out_size)
{
    const float* x   = (const float*)d_in[0];
    const float* gch = (const float*)d_in[1];
    const float* pch = (const float*)d_in[2];
    const float* wq  = (const float*)d_in[3];
    const float* wk  = (const float*)d_in[4];
    const float* wv  = (const float*)d_in[5];
    const float* wo  = (const float*)d_in[6];
    float* out = (float*)d_out;

    float *qp, *kp, *vp, *aop, *wtp;
    cudaGetSymbolAddress((void**)&qp,  g_q);
    cudaGetSymbolAddress((void**)&kp,  g_k);
    cudaGetSymbolAddress((void**)&vp,  g_v);
    cudaGetSymbolAddress((void**)&aop, g_ao);
    cudaGetSymbolAddress((void**)&wtp, g_wt);

    cudaFuncSetAttribute(gemm_qkv3,
                         cudaFuncAttributeMaxDynamicSharedMemorySize, GEMM_SMEM);
    cudaFuncSetAttribute(gemm_out,
                         cudaFuncAttributeMaxDynamicSharedMemorySize, GEMM_SMEM);
    cudaFuncSetAttribute(attn_mma,
                         cudaFuncAttributeMaxDynamicSharedMemorySize, ATTN_SMEM);

    transpose_w<<<dim3(DIMC / 32, DIMC / 32, 4), dim3(32, 8)>>>(wq, wk, wv, wo, wtp);

    gemm_qkv3<<<dim3(DIMC / 128, MROWS / 128, 3), 256, GEMM_SMEM>>>(x, wtp, qp, kp, vp);

    attn_mma<<<dim3(SLEN / 64, NH, BATCH), 128, ATTN_SMEM>>>(qp, kp, vp, x, gch, aop);

    gemm_out<<<dim3(DIMC / 128, MROWS / 128), 256, GEMM_SMEM>>>(aop, wtp, out, x, gch, pch);
}

// round 15
// speedup vs baseline: 1.3327x; 1.3327x over previous
#include <cuda_runtime.h>
#include <math.h>
#include <stdint.h>

#define SLEN  2048
#define DIMC  1024
#define NH    16
#define HDIM  64
#define BATCH 2
#define MROWS (BATCH*SLEN)   /* 4096 */
#define IOS   1008           /* DIM - 16 */

// ---- scratch (allocation-free rule: __device__ globals) ----
__device__ float g_q [(size_t)MROWS * DIMC];
__device__ float g_k [(size_t)MROWS * DIMC];
__device__ float g_v [(size_t)MROWS * DIMC];
__device__ float g_ao[(size_t)MROWS * DIMC];
__device__ float g_wt[(size_t)4 * DIMC * DIMC];   // transposed weights

__device__ __forceinline__ uint32_t f2tf(float f) {
    uint32_t u;
    asm("cvt.rna.tf32.f32 %0, %1;" : "=r"(u) : "f"(f));
    return u;
}

// D = A(16x8 tf32, row) * B(8x8 tf32, col) + D (fp32). fp32 operands truncate (RZ).
__device__ __forceinline__ void mma8(float c[4], const uint32_t a[4], const uint32_t b[2]) {
    asm volatile(
        "mma.sync.aligned.m16n8k8.row.col.f32.tf32.tf32.f32 "
        "{%0,%1,%2,%3}, {%4,%5,%6,%7}, {%8,%9}, {%0,%1,%2,%3};"
        : "+f"(c[0]), "+f"(c[1]), "+f"(c[2]), "+f"(c[3])
        : "r"(a[0]), "r"(a[1]), "r"(a[2]), "r"(a[3]), "r"(b[0]), "r"(b[1]));
}

__device__ __forceinline__ void ldsm4(uint32_t r[4], uint32_t saddr) {
    asm volatile("ldmatrix.sync.aligned.m8n8.x4.shared.b16 {%0,%1,%2,%3}, [%4];"
        : "=r"(r[0]), "=r"(r[1]), "=r"(r[2]), "=r"(r[3]) : "r"(saddr));
}

__device__ __forceinline__ void cpa16(uint32_t saddr, const void* gp) {
    asm volatile("cp.async.cg.shared.global [%0], [%1], 16;" :: "r"(saddr), "l"(gp));
}
__device__ __forceinline__ void cp_commit() {
    asm volatile("cp.async.commit_group;" ::: "memory");
}
template<int N> __device__ __forceinline__ void cp_wait() {
    asm volatile("cp.async.wait_group %0;" :: "n"(N) : "memory");
}

// ============================================================
// Weight transpose: g_wt[z] = W_z^T (k-contiguous rows).
// ============================================================
__global__ __launch_bounds__(256) void transpose_w(
    const float* __restrict__ w0, const float* __restrict__ w1,
    const float* __restrict__ w2, const float* __restrict__ w3,
    float* __restrict__ wt)
{
    __shared__ float t[32][33];
    const float* W = (blockIdx.z == 0) ? w0 : (blockIdx.z == 1) ? w1
                   : (blockIdx.z == 2) ? w2 : w3;
    float* WT = wt + (size_t)blockIdx.z * DIMC * DIMC;
    const int x0 = blockIdx.x * 32, y0 = blockIdx.y * 32;
    #pragma unroll
    for (int i = threadIdx.y; i < 32; i += 8)
        t[i][threadIdx.x] = W[(size_t)(y0 + i) * DIMC + x0 + threadIdx.x];
    __syncthreads();
    #pragma unroll
    for (int i = threadIdx.y; i < 32; i += 8)
        WT[(size_t)(x0 + i) * DIMC + y0 + threadIdx.x] = t[threadIdx.x][i];
}

// ============================================================
// tf32 GEMM (NT) — EXACT R10 configuration (best: 457.5us).
// 128x128 block tile, 8 warps, warp 64x32, K-step 16,
// 3-stage cp.async, static smem, ldmatrix fragment loads.
// ============================================================
#define GS 20              /* smem row stride (words); 20r mod 32 spans all banks */
#define TSTG (128 * GS)    /* words per operand tile stage */
#define GSTG 3

__device__ __forceinline__ void gemm_body(
    const float* __restrict__ A, const float* __restrict__ BT,
    float* __restrict__ C, const float* __restrict__ resid,
    const float* __restrict__ getc, const float* __restrict__ putc,
    bool cvt, float scale, uint32_t* sA, uint32_t* sB)
{
    const int tid = threadIdx.x, lane = tid & 31, w = tid >> 5;
    const int g = lane >> 2, tg = lane & 3;
    const int wm = w >> 2, wn = w & 3;
    const int m0 = blockIdx.y * 128, n0 = blockIdx.x * 128;

    const int r0 = tid >> 2, kc = (tid & 3) * 4;

    const uint32_t sAa = (uint32_t)__cvta_generic_to_shared(sA);
    const uint32_t sBa = (uint32_t)__cvta_generic_to_shared(sB);

    const float* Ap0 = &A [(size_t)(m0 + r0) * DIMC + kc];
    const float* Ap1 = Ap0 + (size_t)64 * DIMC;
    const float* Bp0 = &BT[(size_t)(n0 + r0) * DIMC + kc];
    const float* Bp1 = Bp0 + (size_t)64 * DIMC;
    const uint32_t dA0 = sAa + (r0 * GS + kc) * 4;
    const uint32_t dA1 = sAa + ((r0 + 64) * GS + kc) * 4;
    const uint32_t dB0 = sBa + (r0 * GS + kc) * 4;
    const uint32_t dB1 = sBa + ((r0 + 64) * GS + kc) * 4;

    // per-lane ldmatrix address components
    const uint32_t aLane = ((wm * 64 + (lane & 15)) * GS + ((lane >> 4) & 1) * 4) * 4;
    const uint32_t bLane = ((wn * 32 + (lane & 7) + ((lane >> 4) & 1) * 8) * GS
                            + ((lane >> 3) & 1) * 4) * 4;

    float acc[16][4];
    #pragma unroll
    for (int i = 0; i < 16; i++)
        #pragma unroll
        for (int j = 0; j < 4; j++) acc[i][j] = 0.f;

    #pragma unroll
    for (int s = 0; s < GSTG - 1; s++) {
        const int k0 = s * 16;
        cpa16(dA0 + s * TSTG * 4, Ap0 + k0);
        cpa16(dA1 + s * TSTG * 4, Ap1 + k0);
        cpa16(dB0 + s * TSTG * 4, Bp0 + k0);
        cpa16(dB1 + s * TSTG * 4, Bp1 + k0);
        cp_commit();
    }

    const int KT = DIMC / 16;
    for (int kt = 0; kt < KT; kt++) {
        cp_wait<GSTG - 2>();
        __syncthreads();
        if (kt + GSTG - 1 < KT) {
            const int s = (kt + GSTG - 1) % GSTG;
            const int k0 = (kt + GSTG - 1) * 16;
            cpa16(dA0 + s * TSTG * 4, Ap0 + k0);
            cpa16(dA1 + s * TSTG * 4, Ap1 + k0);
            cpa16(dB0 + s * TSTG * 4, Bp0 + k0);
            cpa16(dB1 + s * TSTG * 4, Bp1 + k0);
        }
        cp_commit();

        const uint32_t aBase = sAa + (kt % GSTG) * TSTG * 4 + aLane;
        const uint32_t bBase = sBa + (kt % GSTG) * TSTG * 4 + bLane;
        #pragma unroll
        for (int ks = 0; ks < 16; ks += 8) {
            uint32_t af[4][4], bf[2][4];
            #pragma unroll
            for (int ma = 0; ma < 4; ma++)
                ldsm4(af[ma], aBase + (ma * 16 * GS + ks) * 4);
            #pragma unroll
            for (int n2 = 0; n2 < 2; n2++)
                ldsm4(bf[n2], bBase + (n2 * 16 * GS + ks) * 4);
            #pragma unroll
            for (int ma = 0; ma < 4; ma++)
                #pragma unroll
                for (int na = 0; na < 4; na++)
                    mma8(acc[ma * 4 + na], af[ma], &bf[na >> 1][(na & 1) * 2]);
        }
    }

    #pragma unroll
    for (int ma = 0; ma < 4; ma++) {
        #pragma unroll
        for (int na = 0; na < 4; na++) {
            const int rbase = m0 + wm * 64 + ma * 16 + g;
            const int cbase = n0 + wn * 32 + na * 8 + 2 * tg;
            #pragma unroll
            for (int half = 0; half < 2; half++) {
                const int m = rbase + 8 * half;
                float v0 = acc[ma * 4 + na][2 * half + 0];
                float v1 = acc[ma * 4 + na][2 * half + 1];
                if (cvt) {
                    v0 = __uint_as_float(f2tf(v0 * scale));
                    v1 = __uint_as_float(f2tf(v1 * scale));
                } else if (resid) {
                    v0 += resid[(size_t)m * DIMC + cbase];
                    v1 += resid[(size_t)m * DIMC + cbase + 1];
                    #pragma unroll
                    for (int c = 0; c < 2; c++) {
                        const int n = cbase + c;
                        float* pv = c ? &v1 : &v0;
                        if (n == IOS + 1)  *pv += getc[m];
                        if (n == IOS + 3)  *pv += putc[m];
                        if (n == IOS + 13) *pv  = putc[m];
                    }
                }
                *(float2*)&C[(size_t)m * DIMC + cbase] = make_float2(v0, v1);
            }
        }
    }
}

__global__ __launch_bounds__(256, 2) void gemm_qkv3(
    const float* __restrict__ x, const float* __restrict__ wt,
    float* __restrict__ q, float* __restrict__ k, float* __restrict__ v)
{
    __shared__ uint32_t sA[GSTG * TSTG];
    __shared__ uint32_t sB[GSTG * TSTG];
    const int z = blockIdx.z;
    const float* BT = wt + (size_t)z * DIMC * DIMC;
    float* C = (z == 0) ? q : (z == 1) ? k : v;
    const float scale = (z == 0) ? 0.125f : 1.0f;
    gemm_body(x, BT, C, nullptr, nullptr, nullptr, true, scale, sA, sB);
}

__global__ __launch_bounds__(256, 2) void gemm_out(
    const float* __restrict__ A, const float* __restrict__ wt,
    float* __restrict__ C, const float* __restrict__ resid,
    const float* __restrict__ getc, const float* __restrict__ putc)
{
    __shared__ uint32_t sA[GSTG * TSTG];
    __shared__ uint32_t sB[GSTG * TSTG];
    gemm_body(A, wt + (size_t)3 * DIMC * DIMC, C, resid, getc, putc, false, 1.0f, sA, sB);
}

// ============================================================
// Flash attention, tf32 mma: NOW 128 q-rows per block, 256 thr
// / 8 warps (warp = 16 rows). K/V tiles amortized over 2x the
// warps => half the global traffic & barriers per MMA.
// ============================================================
#define AS 68
/* sK[2 x 64] + sV[64] + sQP[128] rows, stride AS words */
#define ATTN_SMEM ((2 * 64 + 64 + 128) * AS * 4)

__global__ __launch_bounds__(256, 2) void attn_mma(
    const float* __restrict__ q, const float* __restrict__ k,
    const float* __restrict__ v, const float* __restrict__ x,
    const float* __restrict__ getc, float* __restrict__ ao)
{
    extern __shared__ uint32_t smem[];
    uint32_t* sK  = smem;               // 2 buffers of 64 rows
    uint32_t* sV  = sK + 2 * 64 * AS;   // 64 rows
    uint32_t* sQP = sV + 64 * AS;       // 128 rows: Q staging, then P

    const uint32_t sKa  = (uint32_t)__cvta_generic_to_shared(sK);
    const uint32_t sVa  = (uint32_t)__cvta_generic_to_shared(sV);
    const uint32_t sQPa = (uint32_t)__cvta_generic_to_shared(sQP);

    const int tid = threadIdx.x, lane = tid & 31, w = tid >> 5;   // w: 0..7
    const int g = lane >> 2, tg = lane & 3;
    const int it = gridDim.x - 1 - blockIdx.x;   // heavy blocks first
    const int h = blockIdx.y, b = blockIdx.z;
    const int i0 = it * 128;
    const size_t bS = (size_t)b * SLEN;

    const uint32_t kLane = (((lane & 7) + ((lane >> 4) & 1) * 8) * AS
                            + ((lane >> 3) & 1) * 4) * 4;
    const uint32_t pLane = ((w * 16 + (lane & 15)) * AS + ((lane >> 4) & 1) * 4) * 4;

    // 64x64 tile load slots for 256 threads: 4 chunks
    int lrow[4], lcol[4];
    #pragma unroll
    for (int i = 0; i < 4; i++) {
        const int id = tid + 256 * i;
        lrow[i] = id >> 4; lcol[i] = (id & 15) * 4;
    }

    // stage Q tile (128 rows, tf32-rounded & pre-scaled): 8 chunks
    #pragma unroll
    for (int i = 0; i < 8; i++) {
        const int id = tid + 256 * i;
        const int row = id >> 4, col = (id & 15) * 4;
        cpa16(sQPa + (row * AS + col) * 4,
              &q[(bS + i0 + row) * DIMC + h * HDIM + col]);
    }
    cp_commit(); cp_wait<0>();
    __syncthreads();
    uint32_t afq[8][4];
    #pragma unroll
    for (int k8 = 0; k8 < 8; k8++)
        ldsm4(afq[k8], sQPa + pLane + k8 * 8 * 4);
    __syncthreads();   // sQP now free for P

    const float slope = exp2f(-0.5f * (float)(h + 1));
    const bool h0 = (h == 0);

    float m2[2] = {-INFINITY, -INFINITY}, l2[2] = {0.f, 0.f};
    float O[8][4];
    #pragma unroll
    for (int na = 0; na < 8; na++)
        #pragma unroll
        for (int j = 0; j < 4; j++) O[na][j] = 0.f;

    bool gcf[2]; float tgt[2];
    #pragma unroll
    for (int rs = 0; rs < 2; rs++) {
        const int gi = i0 + w * 16 + g + 8 * rs;
        gcf[rs] = (getc[bS + gi] > 0.5f) && h0;
        const float* xr = &x[(bS + gi) * DIMC + IOS];
        tgt[rs] = xr[0] + 1.0f + xr[1];
    }

    const int njt = h0 ? (SLEN / 64) : (2 * it + 2);

    // prologue: K[0] -> sK buf 0
    #pragma unroll
    for (int i = 0; i < 4; i++)
        cpa16(sKa + (lrow[i] * AS + lcol[i]) * 4,
              &k[(bS + lrow[i]) * DIMC + h * HDIM + lcol[i]]);
    cp_commit();

    for (int jt = 0; jt < njt; jt++) {
        const int j0 = jt * 64;
        const int buf = jt & 1;
        __syncthreads();

        // V[jt] load overlaps GEMM1
        #pragma unroll
        for (int i = 0; i < 4; i++)
            cpa16(sVa + (lrow[i] * AS + lcol[i]) * 4,
                  &v[(bS + j0 + lrow[i]) * DIMC + h * HDIM + lcol[i]]);
        cp_commit();
        cp_wait<1>();
        __syncthreads();

        // GEMM1: S = Q @ K^T (K frags via ldmatrix)
        const uint32_t kBase = sKa + buf * 64 * AS * 4 + kLane;
        float s[8][4];
        #pragma unroll
        for (int na = 0; na < 8; na++)
            #pragma unroll
            for (int j = 0; j < 4; j++) s[na][j] = 0.f;
        #pragma unroll
        for (int k8 = 0; k8 < 8; k8++) {
            uint32_t bf[4][4];
            #pragma unroll
            for (int n2 = 0; n2 < 4; n2++)
                ldsm4(bf[n2], kBase + (n2 * 16 * AS + k8 * 8) * 4);
            #pragma unroll
            for (int na = 0; na < 8; na++)
                mma8(s[na], afq[k8], &bf[na >> 1][(na & 1) * 2]);
        }

        // prefetch next K during softmax + GEMM2
        if (jt + 1 < njt) {
            const int nj0 = (jt + 1) * 64;
            const uint32_t kb = sKa + (buf ^ 1) * 64 * AS * 4;
            #pragma unroll
            for (int i = 0; i < 4; i++)
                cpa16(kb + (lrow[i] * AS + lcol[i]) * 4,
                      &k[(bS + nj0 + lrow[i]) * DIMC + h * HDIM + lcol[i]]);
        }
        cp_commit();

        // bias + online softmax per row-half
        #pragma unroll
        for (int rs = 0; rs < 2; rs++) {
            const int gi = i0 + w * 16 + g + 8 * rs;
            if (gcf[rs]) {
                #pragma unroll
                for (int na = 0; na < 8; na++)
                    #pragma unroll
                    for (int c = 0; c < 2; c++) {
                        const int gj = j0 + na * 8 + 2 * tg + c;
                        s[na][2 * rs + c] = -slope * fabsf(tgt[rs] - (float)gj);
                    }
            } else {
                #pragma unroll
                for (int na = 0; na < 8; na++)
                    #pragma unroll
                    for (int c = 0; c < 2; c++) {
                        const int gj = j0 + na * 8 + 2 * tg + c;
                        s[na][2 * rs + c] = (gj <= gi)
                            ? s[na][2 * rs + c] - slope * (float)(gi - gj) : -1e30f;
                    }
            }
            float tm = -INFINITY;
            #pragma unroll
            for (int na = 0; na < 8; na++)
                tm = fmaxf(tm, fmaxf(s[na][2 * rs], s[na][2 * rs + 1]));
            tm = fmaxf(tm, __shfl_xor_sync(0xffffffffu, tm, 1));
            tm = fmaxf(tm, __shfl_xor_sync(0xffffffffu, tm, 2));
            const float mn = fmaxf(m2[rs], tm);
            const float alpha = __expf(m2[rs] - mn);
            m2[rs] = mn;
            float rsum = 0.f;
            #pragma unroll
            for (int na = 0; na < 8; na++)
                #pragma unroll
                for (int c = 0; c < 2; c++) {
                    float e = __expf(s[na][2 * rs + c] - mn);
                    s[na][2 * rs + c] = e; rsum += e;
                }
            rsum += __shfl_xor_sync(0xffffffffu, rsum, 1);
            rsum += __shfl_xor_sync(0xffffffffu, rsum, 2);
            l2[rs] = l2[rs] * alpha + rsum;
            #pragma unroll
            for (int na = 0; na < 8; na++) {
                O[na][2 * rs + 0] *= alpha;
                O[na][2 * rs + 1] *= alpha;
            }
        }

        cp_wait<1>();       // V_jt done (K_next may pend)
        __syncthreads();

        // P -> sP (warp-private rows), raw fp32 bits (mma truncates)
        #pragma unroll
        for (int na = 0; na < 8; na++) {
            const int r = w * 16 + g, c = na * 8 + 2 * tg;
            sQP[r * AS + c]           = __float_as_uint(s[na][0]);
            sQP[r * AS + c + 1]       = __float_as_uint(s[na][1]);
            sQP[(r + 8) * AS + c]     = __float_as_uint(s[na][2]);
            sQP[(r + 8) * AS + c + 1] = __float_as_uint(s[na][3]);
        }
        __syncwarp();

        // GEMM2: O += P @ V (P frags via ldmatrix; V row-major scalar B)
        #pragma unroll
        for (int k8 = 0; k8 < 8; k8++) {
            uint32_t af[4];
            ldsm4(af, sQPa + pLane + k8 * 8 * 4);
            #pragma unroll
            for (int na = 0; na < 8; na++) {
                uint32_t bf[2];
                const int nb = (k8 * 8 + tg) * AS + na * 8 + g;
                bf[0] = sV[nb]; bf[1] = sV[nb + 4 * AS];
                mma8(O[na], af, bf);
            }
        }
    }

    #pragma unroll
    for (int rs = 0; rs < 2; rs++) {
        const float inv = 1.0f / l2[rs];
        const size_t rowoff = (bS + i0 + w * 16 + g + 8 * rs) * DIMC + h * HDIM;
        #pragma unroll
        for (int na = 0; na < 8; na++) {
            *(float2*)&ao[rowoff + na * 8 + 2 * tg] =
                make_float2(O[na][2 * rs] * inv, O[na][2 * rs + 1] * inv);
        }
    }
}

// ============================================================
extern "C" void kernel_launch(void* const* d_in, const int* in_sizes, int n_in,
                              void* d_out, int out_size)
{
    const float* x   = (const float*)d_in[0];
    const float* gch = (const float*)d_in[1];
    const float* pch = (const float*)d_in[2];
    const float* wq  = (const float*)d_in[3];
    const float* wk  = (const float*)d_in[4];
    const float* wv  = (const float*)d_in[5];
    const float* wo  = (const float*)d_in[6];
    float* out = (float*)d_out;

    float *qp, *kp, *vp, *aop, *wtp;
    cudaGetSymbolAddress((void**)&qp,  g_q);
    cudaGetSymbolAddress((void**)&kp,  g_k);
    cudaGetSymbolAddress((void**)&vp,  g_v);
    cudaGetSymbolAddress((void**)&aop, g_ao);
    cudaGetSymbolAddress((void**)&wtp, g_wt);

    cudaFuncSetAttribute(attn_mma,
                         cudaFuncAttributeMaxDynamicSharedMemorySize, ATTN_SMEM);

    transpose_w<<<dim3(DIMC / 32, DIMC / 32, 4), dim3(32, 8)>>>(wq, wk, wv, wo, wtp);

    gemm_qkv3<<<dim3(DIMC / 128, MROWS / 128, 3), 256>>>(x, wtp, qp, kp, vp);

    attn_mma<<<dim3(SLEN / 128, NH, BATCH), 256, ATTN_SMEM>>>(qp, kp, vp, x, gch, aop);

    gemm_out<<<dim3(DIMC / 128, MROWS / 128), 256>>>(aop, wtp, out, x, gch, pch);
}

// round 16
// speedup vs baseline: 1.3865x; 1.0403x over previous
#include <cuda_runtime.h>
#include <math.h>
#include <stdint.h>

#define SLEN  2048
#define DIMC  1024
#define NH    16
#define HDIM  64
#define BATCH 2
#define MROWS (BATCH*SLEN)   /* 4096 */
#define IOS   1008           /* DIM - 16 */

// ---- scratch (allocation-free rule: __device__ globals) ----
__device__ float g_q [(size_t)MROWS * DIMC];
__device__ float g_k [(size_t)MROWS * DIMC];
__device__ float g_v [(size_t)MROWS * DIMC];
__device__ float g_ao[(size_t)MROWS * DIMC];
__device__ float g_wt[(size_t)4 * DIMC * DIMC];   // transposed weights

__device__ __forceinline__ uint32_t f2tf(float f) {
    uint32_t u;
    asm("cvt.rna.tf32.f32 %0, %1;" : "=r"(u) : "f"(f));
    return u;
}

// D = A(16x8 tf32, row) * B(8x8 tf32, col) + D (fp32). fp32 operands truncate (RZ).
__device__ __forceinline__ void mma8(float c[4], const uint32_t a[4], const uint32_t b[2]) {
    asm volatile(
        "mma.sync.aligned.m16n8k8.row.col.f32.tf32.tf32.f32 "
        "{%0,%1,%2,%3}, {%4,%5,%6,%7}, {%8,%9}, {%0,%1,%2,%3};"
        : "+f"(c[0]), "+f"(c[1]), "+f"(c[2]), "+f"(c[3])
        : "r"(a[0]), "r"(a[1]), "r"(a[2]), "r"(a[3]), "r"(b[0]), "r"(b[1]));
}

__device__ __forceinline__ void ldsm4(uint32_t r[4], uint32_t saddr) {
    asm volatile("ldmatrix.sync.aligned.m8n8.x4.shared.b16 {%0,%1,%2,%3}, [%4];"
        : "=r"(r[0]), "=r"(r[1]), "=r"(r[2]), "=r"(r[3]) : "r"(saddr));
}

__device__ __forceinline__ void cpa16(uint32_t saddr, const void* gp) {
    asm volatile("cp.async.cg.shared.global [%0], [%1], 16;" :: "r"(saddr), "l"(gp));
}
__device__ __forceinline__ void cp_commit() {
    asm volatile("cp.async.commit_group;" ::: "memory");
}
template<int N> __device__ __forceinline__ void cp_wait() {
    asm volatile("cp.async.wait_group %0;" :: "n"(N) : "memory");
}

// ============================================================
// Weight transpose: g_wt[z] = W_z^T (k-contiguous rows).
// ============================================================
__global__ __launch_bounds__(256) void transpose_w(
    const float* __restrict__ w0, const float* __restrict__ w1,
    const float* __restrict__ w2, const float* __restrict__ w3,
    float* __restrict__ wt)
{
    __shared__ float t[32][33];
    const float* W = (blockIdx.z == 0) ? w0 : (blockIdx.z == 1) ? w1
                   : (blockIdx.z == 2) ? w2 : w3;
    float* WT = wt + (size_t)blockIdx.z * DIMC * DIMC;
    const int x0 = blockIdx.x * 32, y0 = blockIdx.y * 32;
    #pragma unroll
    for (int i = threadIdx.y; i < 32; i += 8)
        t[i][threadIdx.x] = W[(size_t)(y0 + i) * DIMC + x0 + threadIdx.x];
    __syncthreads();
    #pragma unroll
    for (int i = threadIdx.y; i < 32; i += 8)
        WT[(size_t)(x0 + i) * DIMC + y0 + threadIdx.x] = t[threadIdx.x][i];
}

// ============================================================
// tf32 GEMM (NT) — EXACT R10 configuration (best: 457.5us).
// 128x128 block tile, 8 warps, warp 64x32, K-step 16,
// 3-stage cp.async, static smem, ldmatrix fragment loads.
// ============================================================
#define GS 20              /* smem row stride (words); 20r mod 32 spans all banks */
#define TSTG (128 * GS)    /* words per operand tile stage */
#define GSTG 3

__device__ __forceinline__ void gemm_body(
    const float* __restrict__ A, const float* __restrict__ BT,
    float* __restrict__ C, const float* __restrict__ resid,
    const float* __restrict__ getc, const float* __restrict__ putc,
    bool cvt, float scale, uint32_t* sA, uint32_t* sB)
{
    const int tid = threadIdx.x, lane = tid & 31, w = tid >> 5;
    const int g = lane >> 2, tg = lane & 3;
    const int wm = w >> 2, wn = w & 3;
    const int m0 = blockIdx.y * 128, n0 = blockIdx.x * 128;

    const int r0 = tid >> 2, kc = (tid & 3) * 4;

    const uint32_t sAa = (uint32_t)__cvta_generic_to_shared(sA);
    const uint32_t sBa = (uint32_t)__cvta_generic_to_shared(sB);

    const float* Ap0 = &A [(size_t)(m0 + r0) * DIMC + kc];
    const float* Ap1 = Ap0 + (size_t)64 * DIMC;
    const float* Bp0 = &BT[(size_t)(n0 + r0) * DIMC + kc];
    const float* Bp1 = Bp0 + (size_t)64 * DIMC;
    const uint32_t dA0 = sAa + (r0 * GS + kc) * 4;
    const uint32_t dA1 = sAa + ((r0 + 64) * GS + kc) * 4;
    const uint32_t dB0 = sBa + (r0 * GS + kc) * 4;
    const uint32_t dB1 = sBa + ((r0 + 64) * GS + kc) * 4;

    // per-lane ldmatrix address components
    const uint32_t aLane = ((wm * 64 + (lane & 15)) * GS + ((lane >> 4) & 1) * 4) * 4;
    const uint32_t bLane = ((wn * 32 + (lane & 7) + ((lane >> 4) & 1) * 8) * GS
                            + ((lane >> 3) & 1) * 4) * 4;

    float acc[16][4];
    #pragma unroll
    for (int i = 0; i < 16; i++)
        #pragma unroll
        for (int j = 0; j < 4; j++) acc[i][j] = 0.f;

    #pragma unroll
    for (int s = 0; s < GSTG - 1; s++) {
        const int k0 = s * 16;
        cpa16(dA0 + s * TSTG * 4, Ap0 + k0);
        cpa16(dA1 + s * TSTG * 4, Ap1 + k0);
        cpa16(dB0 + s * TSTG * 4, Bp0 + k0);
        cpa16(dB1 + s * TSTG * 4, Bp1 + k0);
        cp_commit();
    }

    const int KT = DIMC / 16;
    for (int kt = 0; kt < KT; kt++) {
        cp_wait<GSTG - 2>();
        __syncthreads();
        if (kt + GSTG - 1 < KT) {
            const int s = (kt + GSTG - 1) % GSTG;
            const int k0 = (kt + GSTG - 1) * 16;
            cpa16(dA0 + s * TSTG * 4, Ap0 + k0);
            cpa16(dA1 + s * TSTG * 4, Ap1 + k0);
            cpa16(dB0 + s * TSTG * 4, Bp0 + k0);
            cpa16(dB1 + s * TSTG * 4, Bp1 + k0);
        }
        cp_commit();

        const uint32_t aBase = sAa + (kt % GSTG) * TSTG * 4 + aLane;
        const uint32_t bBase = sBa + (kt % GSTG) * TSTG * 4 + bLane;
        #pragma unroll
        for (int ks = 0; ks < 16; ks += 8) {
            uint32_t af[4][4], bf[2][4];
            #pragma unroll
            for (int ma = 0; ma < 4; ma++)
                ldsm4(af[ma], aBase + (ma * 16 * GS + ks) * 4);
            #pragma unroll
            for (int n2 = 0; n2 < 2; n2++)
                ldsm4(bf[n2], bBase + (n2 * 16 * GS + ks) * 4);
            #pragma unroll
            for (int ma = 0; ma < 4; ma++)
                #pragma unroll
                for (int na = 0; na < 4; na++)
                    mma8(acc[ma * 4 + na], af[ma], &bf[na >> 1][(na & 1) * 2]);
        }
    }

    #pragma unroll
    for (int ma = 0; ma < 4; ma++) {
        #pragma unroll
        for (int na = 0; na < 4; na++) {
            const int rbase = m0 + wm * 64 + ma * 16 + g;
            const int cbase = n0 + wn * 32 + na * 8 + 2 * tg;
            #pragma unroll
            for (int half = 0; half < 2; half++) {
                const int m = rbase + 8 * half;
                float v0 = acc[ma * 4 + na][2 * half + 0];
                float v1 = acc[ma * 4 + na][2 * half + 1];
                if (cvt) {
                    v0 = __uint_as_float(f2tf(v0 * scale));
                    v1 = __uint_as_float(f2tf(v1 * scale));
                } else if (resid) {
                    v0 += resid[(size_t)m * DIMC + cbase];
                    v1 += resid[(size_t)m * DIMC + cbase + 1];
                    #pragma unroll
                    for (int c = 0; c < 2; c++) {
                        const int n = cbase + c;
                        float* pv = c ? &v1 : &v0;
                        if (n == IOS + 1)  *pv += getc[m];
                        if (n == IOS + 3)  *pv += putc[m];
                        if (n == IOS + 13) *pv  = putc[m];
                    }
                }
                *(float2*)&C[(size_t)m * DIMC + cbase] = make_float2(v0, v1);
            }
        }
    }
}

__global__ __launch_bounds__(256, 2) void gemm_qkv3(
    const float* __restrict__ x, const float* __restrict__ wt,
    float* __restrict__ q, float* __restrict__ k, float* __restrict__ v)
{
    __shared__ uint32_t sA[GSTG * TSTG];
    __shared__ uint32_t sB[GSTG * TSTG];
    const int z = blockIdx.z;
    const float* BT = wt + (size_t)z * DIMC * DIMC;
    float* C = (z == 0) ? q : (z == 1) ? k : v;
    const float scale = (z == 0) ? 0.125f : 1.0f;
    gemm_body(x, BT, C, nullptr, nullptr, nullptr, true, scale, sA, sB);
}

__global__ __launch_bounds__(256, 2) void gemm_out(
    const float* __restrict__ A, const float* __restrict__ wt,
    float* __restrict__ C, const float* __restrict__ resid,
    const float* __restrict__ getc, const float* __restrict__ putc)
{
    __shared__ uint32_t sA[GSTG * TSTG];
    __shared__ uint32_t sB[GSTG * TSTG];
    gemm_body(A, wt + (size_t)3 * DIMC * DIMC, C, resid, getc, putc, false, 1.0f, sA, sB);
}

// ============================================================
// Flash attention, tf32 mma — R10 structure (64-row tiles,
// 128 thr / 4 warps) with STATIC-MAX softmax:
// p = exp(s - 16); no running max, no rescale, no per-tile
// shuffles. l reduced once at the end. Scores are bounded
// (|s| <~ 5), so exp(s-16) can't overflow; masked terms -> 0.
// ============================================================
#define AS 68
#define ATTN_SMEM (4 * 64 * AS * 4)   /* sK[2] + sV + sQP */
#define SMAX 16.0f

__global__ __launch_bounds__(128, 3) void attn_mma(
    const float* __restrict__ q, const float* __restrict__ k,
    const float* __restrict__ v, const float* __restrict__ x,
    const float* __restrict__ getc, float* __restrict__ ao)
{
    extern __shared__ uint32_t smem[];
    uint32_t* sK  = smem;               // 2 buffers
    uint32_t* sV  = sK + 2 * 64 * AS;
    uint32_t* sQP = sV + 64 * AS;

    const uint32_t sKa  = (uint32_t)__cvta_generic_to_shared(sK);
    const uint32_t sVa  = (uint32_t)__cvta_generic_to_shared(sV);
    const uint32_t sQPa = (uint32_t)__cvta_generic_to_shared(sQP);

    const int tid = threadIdx.x, lane = tid & 31, w = tid >> 5;
    const int g = lane >> 2, tg = lane & 3;
    const int it = gridDim.x - 1 - blockIdx.x;   // heavy blocks first
    const int h = blockIdx.y, b = blockIdx.z;
    const int i0 = it * 64;
    const size_t bS = (size_t)b * SLEN;

    const uint32_t kLane = (((lane & 7) + ((lane >> 4) & 1) * 8) * AS
                            + ((lane >> 3) & 1) * 4) * 4;
    const uint32_t pLane = ((w * 16 + (lane & 15)) * AS + ((lane >> 4) & 1) * 4) * 4;

    int lrow[8], lcol[8];
    #pragma unroll
    for (int i = 0; i < 8; i++) {
        const int id = tid + 128 * i;
        lrow[i] = id >> 4; lcol[i] = (id & 15) * 4;
    }

    // stage Q tile (tf32-rounded, pre-scaled) and hoist fragments
    #pragma unroll
    for (int i = 0; i < 8; i++)
        cpa16(sQPa + (lrow[i] * AS + lcol[i]) * 4,
              &q[(bS + i0 + lrow[i]) * DIMC + h * HDIM + lcol[i]]);
    cp_commit(); cp_wait<0>();
    __syncthreads();
    uint32_t afq[8][4];
    #pragma unroll
    for (int k8 = 0; k8 < 8; k8++)
        ldsm4(afq[k8], sQPa + pLane + k8 * 8 * 4);
    __syncthreads();   // sQP now free for P

    const float slope = exp2f(-0.5f * (float)(h + 1));
    const bool h0 = (h == 0);

    float l2[2] = {0.f, 0.f};
    float O[8][4];
    #pragma unroll
    for (int na = 0; na < 8; na++)
        #pragma unroll
        for (int j = 0; j < 4; j++) O[na][j] = 0.f;

    bool gcf[2]; float tgt[2];
    #pragma unroll
    for (int rs = 0; rs < 2; rs++) {
        const int gi = i0 + w * 16 + g + 8 * rs;
        gcf[rs] = (getc[bS + gi] > 0.5f) && h0;
        const float* xr = &x[(bS + gi) * DIMC + IOS];
        tgt[rs] = xr[0] + 1.0f + xr[1];
    }

    const int njt = h0 ? (SLEN / 64) : (it + 1);

    // prologue: K[0] -> sK buf 0
    #pragma unroll
    for (int i = 0; i < 8; i++)
        cpa16(sKa + (lrow[i] * AS + lcol[i]) * 4,
              &k[(bS + lrow[i]) * DIMC + h * HDIM + lcol[i]]);
    cp_commit();

    for (int jt = 0; jt < njt; jt++) {
        const int j0 = jt * 64;
        const int buf = jt & 1;
        __syncthreads();

        // V[jt] load overlaps GEMM1
        #pragma unroll
        for (int i = 0; i < 8; i++)
            cpa16(sVa + (lrow[i] * AS + lcol[i]) * 4,
                  &v[(bS + j0 + lrow[i]) * DIMC + h * HDIM + lcol[i]]);
        cp_commit();
        cp_wait<1>();
        __syncthreads();

        // GEMM1: S = Q @ K^T (K frags via ldmatrix)
        const uint32_t kBase = sKa + buf * 64 * AS * 4 + kLane;
        float s[8][4];
        #pragma unroll
        for (int na = 0; na < 8; na++)
            #pragma unroll
            for (int j = 0; j < 4; j++) s[na][j] = 0.f;
        #pragma unroll
        for (int k8 = 0; k8 < 8; k8++) {
            uint32_t bf[4][4];
            #pragma unroll
            for (int n2 = 0; n2 < 4; n2++)
                ldsm4(bf[n2], kBase + (n2 * 16 * AS + k8 * 8) * 4);
            #pragma unroll
            for (int na = 0; na < 8; na++)
                mma8(s[na], afq[k8], &bf[na >> 1][(na & 1) * 2]);
        }

        // prefetch next K during softmax + GEMM2
        if (jt + 1 < njt) {
            const int nj0 = (jt + 1) * 64;
            const uint32_t kb = sKa + (buf ^ 1) * 64 * AS * 4;
            #pragma unroll
            for (int i = 0; i < 8; i++)
                cpa16(kb + (lrow[i] * AS + lcol[i]) * 4,
                      &k[(bS + nj0 + lrow[i]) * DIMC + h * HDIM + lcol[i]]);
        }
        cp_commit();

        // static-max softmax: p = exp(s + bias - SMAX); local partial sums
        #pragma unroll
        for (int rs = 0; rs < 2; rs++) {
            const int gi = i0 + w * 16 + g + 8 * rs;
            float rsum = 0.f;
            if (gcf[rs]) {
                #pragma unroll
                for (int na = 0; na < 8; na++)
                    #pragma unroll
                    for (int c = 0; c < 2; c++) {
                        const int gj = j0 + na * 8 + 2 * tg + c;
                        float e = __expf(-slope * fabsf(tgt[rs] - (float)gj) - SMAX);
                        s[na][2 * rs + c] = e; rsum += e;
                    }
            } else {
                #pragma unroll
                for (int na = 0; na < 8; na++)
                    #pragma unroll
                    for (int c = 0; c < 2; c++) {
                        const int gj = j0 + na * 8 + 2 * tg + c;
                        float e = (gj <= gi)
                            ? __expf(s[na][2 * rs + c] - slope * (float)(gi - gj) - SMAX)
                            : 0.f;
                        s[na][2 * rs + c] = e; rsum += e;
                    }
            }
            l2[rs] += rsum;
        }

        cp_wait<1>();       // V_jt done (K_next may pend)
        __syncthreads();

        // P -> sP (warp-private rows), raw fp32 bits (mma truncates)
        #pragma unroll
        for (int na = 0; na < 8; na++) {
            const int r = w * 16 + g, c = na * 8 + 2 * tg;
            sQP[r * AS + c]           = __float_as_uint(s[na][0]);
            sQP[r * AS + c + 1]       = __float_as_uint(s[na][1]);
            sQP[(r + 8) * AS + c]     = __float_as_uint(s[na][2]);
            sQP[(r + 8) * AS + c + 1] = __float_as_uint(s[na][3]);
        }
        __syncwarp();

        // GEMM2: O += P @ V (P frags via ldmatrix; V row-major scalar B)
        #pragma unroll
        for (int k8 = 0; k8 < 8; k8++) {
            uint32_t af[4];
            ldsm4(af, sQPa + pLane + k8 * 8 * 4);
            #pragma unroll
            for (int na = 0; na < 8; na++) {
                uint32_t bf[2];
                const int nb = (k8 * 8 + tg) * AS + na * 8 + g;
                bf[0] = sV[nb]; bf[1] = sV[nb + 4 * AS];
                mma8(O[na], af, bf);
            }
        }
    }

    // final l reduction (once, not per tile)
    #pragma unroll
    for (int rs = 0; rs < 2; rs++) {
        l2[rs] += __shfl_xor_sync(0xffffffffu, l2[rs], 1);
        l2[rs] += __shfl_xor_sync(0xffffffffu, l2[rs], 2);
    }

    #pragma unroll
    for (int rs = 0; rs < 2; rs++) {
        const float inv = 1.0f / l2[rs];
        const size_t rowoff = (bS + i0 + w * 16 + g + 8 * rs) * DIMC + h * HDIM;
        #pragma unroll
        for (int na = 0; na < 8; na++) {
            *(float2*)&ao[rowoff + na * 8 + 2 * tg] =
                make_float2(O[na][2 * rs] * inv, O[na][2 * rs + 1] * inv);
        }
    }
}

// ============================================================
extern "C" void kernel_launch(void* const* d_in, const int* in_sizes, int n_in,
                              void* d_out, int out_size)
{
    const float* x   = (const float*)d_in[0];
    const float* gch = (const float*)d_in[1];
    const float* pch = (const float*)d_in[2];
    const float* wq  = (const float*)d_in[3];
    const float* wk  = (const float*)d_in[4];
    const float* wv  = (const float*)d_in[5];
    const float* wo  = (const float*)d_in[6];
    float* out = (float*)d_out;

    float *qp, *kp, *vp, *aop, *wtp;
    cudaGetSymbolAddress((void**)&qp,  g_q);
    cudaGetSymbolAddress((void**)&kp,  g_k);
    cudaGetSymbolAddress((void**)&vp,  g_v);
    cudaGetSymbolAddress((void**)&aop, g_ao);
    cudaGetSymbolAddress((void**)&wtp, g_wt);

    cudaFuncSetAttribute(attn_mma,
                         cudaFuncAttributeMaxDynamicSharedMemorySize, ATTN_SMEM);

    transpose_w<<<dim3(DIMC / 32, DIMC / 32, 4), dim3(32, 8)>>>(wq, wk, wv, wo, wtp);

    gemm_qkv3<<<dim3(DIMC / 128, MROWS / 128, 3), 256>>>(x, wtp, qp, kp, vp);

    attn_mma<<<dim3(SLEN / 64, NH, BATCH), 128, ATTN_SMEM>>>(qp, kp, vp, x, gch, aop);

    gemm_out<<<dim3(DIMC / 128, MROWS / 128), 256>>>(aop, wtp, out, x, gch, pch);
}

// round 17
// speedup vs baseline: 2.3778x; 1.7150x over previous
#include <cuda_runtime.h>
#include <cuda_fp16.h>
#include <math.h>
#include <stdint.h>

#define SLEN  2048
#define DIMC  1024
#define NH    16
#define HDIM  64
#define BATCH 2
#define MROWS (BATCH*SLEN)   /* 4096 */
#define IOS   1008           /* DIM - 16 */

// ---- scratch (allocation-free rule: __device__ globals) ----
__device__ __half g_q [(size_t)MROWS * DIMC];
__device__ __half g_k [(size_t)MROWS * DIMC];
__device__ __half g_v [(size_t)MROWS * DIMC];
__device__ __half g_ao[(size_t)MROWS * DIMC];
__device__ __half g_xh[(size_t)MROWS * DIMC];
__device__ __half g_wt[(size_t)4 * DIMC * DIMC];   // transposed fp16 weights

// D = A(16x16 f16, row) * B(16x8 f16, col) + D (fp32 accum)
__device__ __forceinline__ void mma16(float c[4], const uint32_t a[4], const uint32_t b[2]) {
    asm volatile(
        "mma.sync.aligned.m16n8k16.row.col.f32.f16.f16.f32 "
        "{%0,%1,%2,%3}, {%4,%5,%6,%7}, {%8,%9}, {%0,%1,%2,%3};"
        : "+f"(c[0]), "+f"(c[1]), "+f"(c[2]), "+f"(c[3])
        : "r"(a[0]), "r"(a[1]), "r"(a[2]), "r"(a[3]), "r"(b[0]), "r"(b[1]));
}

__device__ __forceinline__ void ldsm4(uint32_t r[4], uint32_t saddr) {
    asm volatile("ldmatrix.sync.aligned.m8n8.x4.shared.b16 {%0,%1,%2,%3}, [%4];"
        : "=r"(r[0]), "=r"(r[1]), "=r"(r[2]), "=r"(r[3]) : "r"(saddr));
}
__device__ __forceinline__ void ldsm4t(uint32_t r[4], uint32_t saddr) {
    asm volatile("ldmatrix.sync.aligned.m8n8.x4.trans.shared.b16 {%0,%1,%2,%3}, [%4];"
        : "=r"(r[0]), "=r"(r[1]), "=r"(r[2]), "=r"(r[3]) : "r"(saddr));
}

__device__ __forceinline__ void cpa16(uint32_t saddr, const void* gp) {
    asm volatile("cp.async.cg.shared.global [%0], [%1], 16;" :: "r"(saddr), "l"(gp));
}
__device__ __forceinline__ void cp_commit() {
    asm volatile("cp.async.commit_group;" ::: "memory");
}
template<int N> __device__ __forceinline__ void cp_wait() {
    asm volatile("cp.async.wait_group %0;" :: "n"(N) : "memory");
}

// ============================================================
// x (fp32) -> fp16
// ============================================================
__global__ __launch_bounds__(256) void xcvt(
    const float* __restrict__ x, __half* __restrict__ xh)
{
    const size_t i = ((size_t)blockIdx.x * 256 + threadIdx.x) * 4;
    float4 v = *(const float4*)(x + i);
    *(__half2*)(xh + i)     = __floats2half2_rn(v.x, v.y);
    *(__half2*)(xh + i + 2) = __floats2half2_rn(v.z, v.w);
}

// ============================================================
// Weight transpose + fp16 convert: g_wt[z] = half(W_z^T).
// ============================================================
__global__ __launch_bounds__(256) void transpose_w(
    const float* __restrict__ w0, const float* __restrict__ w1,
    const float* __restrict__ w2, const float* __restrict__ w3,
    __half* __restrict__ wt)
{
    __shared__ float t[32][33];
    const float* W = (blockIdx.z == 0) ? w0 : (blockIdx.z == 1) ? w1
                   : (blockIdx.z == 2) ? w2 : w3;
    __half* WT = wt + (size_t)blockIdx.z * DIMC * DIMC;
    const int x0 = blockIdx.x * 32, y0 = blockIdx.y * 32;
    #pragma unroll
    for (int i = threadIdx.y; i < 32; i += 8)
        t[i][threadIdx.x] = W[(size_t)(y0 + i) * DIMC + x0 + threadIdx.x];
    __syncthreads();
    #pragma unroll
    for (int i = threadIdx.y; i < 32; i += 8)
        WT[(size_t)(x0 + i) * DIMC + y0 + threadIdx.x] = __float2half(t[threadIdx.x][i]);
}

// ============================================================
// fp16 GEMM (NT): C = A @ BT^T, both operands k-contiguous fp16.
// 128x128 block tile, 8 warps, warp 64x32, K-step 16 (one
// m16n8k16 chunk/stage), 3-stage cp.async, static smem,
// ldmatrix fragments. Mirrors the proven R10 schedule with
// half the traffic per barrier.
// ============================================================
#define GSB  48            /* bytes per smem row: 32 data + 16 pad (conflict-free) */
#define STGB (128 * GSB)   /* 6144 B per operand per stage */
#define GSTG 3

template<bool OUTH>
__device__ __forceinline__ void gemm_body16(
    const __half* __restrict__ A, const __half* __restrict__ BT, void* Cv,
    const float* __restrict__ resid, const float* __restrict__ getc,
    const float* __restrict__ putc, float scale)
{
    __shared__ __align__(16) char sA[GSTG * STGB];
    __shared__ __align__(16) char sB[GSTG * STGB];

    const int tid = threadIdx.x, lane = tid & 31, w = tid >> 5;
    const int g = lane >> 2, tg = lane & 3;
    const int wm = w >> 2, wn = w & 3;
    const int m0 = blockIdx.y * 128, n0 = blockIdx.x * 128;

    const int lrow = tid >> 1;          // 0..127
    const int lkh  = (tid & 1) * 8;     // halves offset within k16

    const uint32_t sAa = (uint32_t)__cvta_generic_to_shared(sA);
    const uint32_t sBa = (uint32_t)__cvta_generic_to_shared(sB);

    const __half* Ap = A  + (size_t)(m0 + lrow) * DIMC + lkh;
    const __half* Bp = BT + (size_t)(n0 + lrow) * DIMC + lkh;
    const uint32_t dA = sAa + lrow * GSB + (tid & 1) * 16;
    const uint32_t dB = sBa + lrow * GSB + (tid & 1) * 16;

    const uint32_t aLane = (wm * 64 + (lane & 15)) * GSB + ((lane >> 4) & 1) * 16;
    const uint32_t bLane = (wn * 32 + ((lane >> 4) & 1) * 8 + (lane & 7)) * GSB
                           + ((lane >> 3) & 1) * 16;

    float acc[16][4];
    #pragma unroll
    for (int i = 0; i < 16; i++)
        #pragma unroll
        for (int j = 0; j < 4; j++) acc[i][j] = 0.f;

    #pragma unroll
    for (int s = 0; s < GSTG - 1; s++) {
        cpa16(dA + s * STGB, Ap + s * 16);
        cpa16(dB + s * STGB, Bp + s * 16);
        cp_commit();
    }

    const int KT = DIMC / 16;
    for (int kt = 0; kt < KT; kt++) {
        cp_wait<GSTG - 2>();
        __syncthreads();
        if (kt + GSTG - 1 < KT) {
            const int s = (kt + GSTG - 1) % GSTG;
            cpa16(dA + s * STGB, Ap + (kt + GSTG - 1) * 16);
            cpa16(dB + s * STGB, Bp + (kt + GSTG - 1) * 16);
        }
        cp_commit();

        const uint32_t base = (kt % GSTG) * STGB;
        uint32_t af[4][4], bf[2][4];
        #pragma unroll
        for (int ma = 0; ma < 4; ma++)
            ldsm4(af[ma], sAa + base + aLane + ma * 16 * GSB);
        #pragma unroll
        for (int n2 = 0; n2 < 2; n2++)
            ldsm4(bf[n2], sBa + base + bLane + n2 * 16 * GSB);
        #pragma unroll
        for (int ma = 0; ma < 4; ma++)
            #pragma unroll
            for (int na = 0; na < 4; na++)
                mma16(acc[ma * 4 + na], af[ma], &bf[na >> 1][(na & 1) * 2]);
    }

    #pragma unroll
    for (int ma = 0; ma < 4; ma++) {
        #pragma unroll
        for (int na = 0; na < 4; na++) {
            const int rbase = m0 + wm * 64 + ma * 16 + g;
            const int cbase = n0 + wn * 32 + na * 8 + 2 * tg;
            #pragma unroll
            for (int half = 0; half < 2; half++) {
                const int m = rbase + 8 * half;
                float v0 = acc[ma * 4 + na][2 * half + 0];
                float v1 = acc[ma * 4 + na][2 * half + 1];
                if (OUTH) {
                    __half* C = (__half*)Cv;
                    *(__half2*)&C[(size_t)m * DIMC + cbase] =
                        __floats2half2_rn(v0 * scale, v1 * scale);
                } else {
                    float* C = (float*)Cv;
                    v0 += resid[(size_t)m * DIMC + cbase];
                    v1 += resid[(size_t)m * DIMC + cbase + 1];
                    #pragma unroll
                    for (int c = 0; c < 2; c++) {
                        const int n = cbase + c;
                        float* pv = c ? &v1 : &v0;
                        if (n == IOS + 1)  *pv += getc[m];
                        if (n == IOS + 3)  *pv += putc[m];
                        if (n == IOS + 13) *pv  = putc[m];
                    }
                    *(float2*)&C[(size_t)m * DIMC + cbase] = make_float2(v0, v1);
                }
            }
        }
    }
}

__global__ __launch_bounds__(256, 2) void gemm_qkv3(
    const __half* __restrict__ xh, const __half* __restrict__ wt,
    __half* __restrict__ q, __half* __restrict__ k, __half* __restrict__ v)
{
    const int z = blockIdx.z;
    const __half* BT = wt + (size_t)z * DIMC * DIMC;
    __half* C = (z == 0) ? q : (z == 1) ? k : v;
    const float scale = (z == 0) ? 0.125f : 1.0f;
    gemm_body16<true>(xh, BT, C, nullptr, nullptr, nullptr, scale);
}

__global__ __launch_bounds__(256, 2) void gemm_out(
    const __half* __restrict__ A, const __half* __restrict__ wt,
    float* __restrict__ C, const float* __restrict__ resid,
    const float* __restrict__ getc, const float* __restrict__ putc)
{
    gemm_body16<false>(A, wt + (size_t)3 * DIMC * DIMC, C, resid, getc, putc, 1.0f);
}

// ============================================================
// Flash attention, fp16 mma (m16n8k16), R10 structure:
// 64-row i-tiles, 128 thr / 4 warps (warp = 16 q-rows),
// double-buffered K, V overlaps GEMM1, next-K prefetch.
// Static softmax (offset 0: scores bounded, p = exp(s+bias)
// is O(1) and fp16-normal). V consumed row-major via
// ldmatrix.trans. P converted to fp16 for GEMM2.
// ============================================================
#define VSTR   144            /* bytes per 64-half row (128 data + 16 pad) */
#define TILE_B (64 * VSTR)    /* 9216 B per 64-row tile */

__global__ __launch_bounds__(128, 4) void attn_mma(
    const __half* __restrict__ q, const __half* __restrict__ k,
    const __half* __restrict__ v, const float* __restrict__ x,
    const float* __restrict__ getc, __half* __restrict__ ao)
{
    __shared__ __align__(16) char smem[4 * TILE_B];   // sK[2] + sV + sQP = 36.9 KB
    char* sK  = smem;
    char* sV  = smem + 2 * TILE_B;
    char* sQP = smem + 3 * TILE_B;

    const uint32_t sKa  = (uint32_t)__cvta_generic_to_shared(sK);
    const uint32_t sVa  = (uint32_t)__cvta_generic_to_shared(sV);
    const uint32_t sQPa = (uint32_t)__cvta_generic_to_shared(sQP);

    const int tid = threadIdx.x, lane = tid & 31, w = tid >> 5;
    const int g = lane >> 2, tg = lane & 3;
    const int it = gridDim.x - 1 - blockIdx.x;   // heavy blocks first
    const int h = blockIdx.y, b = blockIdx.z;
    const int i0 = it * 64;
    const size_t bS = (size_t)b * SLEN;

    // ldmatrix lane address components
    const uint32_t pLane = (w * 16 + (lane & 15)) * VSTR + ((lane >> 4) & 1) * 16;
    const uint32_t kLane = ((lane & 7) + ((lane >> 4) & 1) * 8) * VSTR
                           + ((lane >> 3) & 1) * 16;
    const uint32_t vLane = ((lane & 7) + ((lane >> 3) & 1) * 8) * VSTR
                           + ((lane >> 4) & 1) * 16;

    // tile-load slots: 64 rows x 128B = 512 x 16B chunks -> 4 per thread
    int trow[4], thoff[4];
    #pragma unroll
    for (int i = 0; i < 4; i++) {
        const int id = tid + 128 * i;
        trow[i] = id >> 3; thoff[i] = (id & 7) * 8;   // halves
    }

    // stage Q (fp16, pre-scaled) and hoist A-fragments
    #pragma unroll
    for (int i = 0; i < 4; i++)
        cpa16(sQPa + trow[i] * VSTR + thoff[i] * 2,
              &q[(bS + i0 + trow[i]) * DIMC + h * HDIM + thoff[i]]);
    cp_commit(); cp_wait<0>();
    __syncthreads();
    uint32_t afq[4][4];
    #pragma unroll
    for (int dc = 0; dc < 4; dc++)
        ldsm4(afq[dc], sQPa + pLane + dc * 32);
    __syncthreads();   // sQP now free for P

    const float slope = exp2f(-0.5f * (float)(h + 1));
    const bool h0 = (h == 0);

    float l2[2] = {0.f, 0.f};
    float O[8][4];
    #pragma unroll
    for (int na = 0; na < 8; na++)
        #pragma unroll
        for (int j = 0; j < 4; j++) O[na][j] = 0.f;

    bool gcf[2]; float tgt[2];
    #pragma unroll
    for (int rs = 0; rs < 2; rs++) {
        const int gi = i0 + w * 16 + g + 8 * rs;
        gcf[rs] = (getc[bS + gi] > 0.5f) && h0;
        const float* xr = &x[(bS + gi) * DIMC + IOS];
        tgt[rs] = xr[0] + 1.0f + xr[1];
    }

    const int njt = h0 ? (SLEN / 64) : (it + 1);

    // prologue: K[0] -> sK buf 0
    #pragma unroll
    for (int i = 0; i < 4; i++)
        cpa16(sKa + trow[i] * VSTR + thoff[i] * 2,
              &k[(bS + trow[i]) * DIMC + h * HDIM + thoff[i]]);
    cp_commit();

    for (int jt = 0; jt < njt; jt++) {
        const int j0 = jt * 64;
        const int buf = jt & 1;
        __syncthreads();

        // V[jt] load overlaps GEMM1
        #pragma unroll
        for (int i = 0; i < 4; i++)
            cpa16(sVa + trow[i] * VSTR + thoff[i] * 2,
                  &v[(bS + j0 + trow[i]) * DIMC + h * HDIM + thoff[i]]);
        cp_commit();
        cp_wait<1>();
        __syncthreads();

        // GEMM1: S = Q @ K^T (K is k-contiguous B; no trans)
        const uint32_t kBase = sKa + buf * TILE_B;
        float s[8][4];
        #pragma unroll
        for (int na = 0; na < 8; na++)
            #pragma unroll
            for (int j = 0; j < 4; j++) s[na][j] = 0.f;
        #pragma unroll
        for (int dc = 0; dc < 4; dc++) {
            uint32_t bf[4][4];
            #pragma unroll
            for (int n2 = 0; n2 < 4; n2++)
                ldsm4(bf[n2], kBase + kLane + n2 * 16 * VSTR + dc * 32);
            #pragma unroll
            for (int na = 0; na < 8; na++)
                mma16(s[na], afq[dc], &bf[na >> 1][(na & 1) * 2]);
        }

        // prefetch next K during softmax + GEMM2
        if (jt + 1 < njt) {
            const int nj0 = (jt + 1) * 64;
            const uint32_t kb = sKa + (buf ^ 1) * TILE_B;
            #pragma unroll
            for (int i = 0; i < 4; i++)
                cpa16(kb + trow[i] * VSTR + thoff[i] * 2,
                      &k[(bS + nj0 + trow[i]) * DIMC + h * HDIM + thoff[i]]);
        }
        cp_commit();

        // static softmax: p = exp(s + bias); scores bounded -> p is O(1)
        #pragma unroll
        for (int rs = 0; rs < 2; rs++) {
            const int gi = i0 + w * 16 + g + 8 * rs;
            float rsum = 0.f;
            if (gcf[rs]) {
                #pragma unroll
                for (int na = 0; na < 8; na++)
                    #pragma unroll
                    for (int c = 0; c < 2; c++) {
                        const int gj = j0 + na * 8 + 2 * tg + c;
                        float e = __expf(-slope * fabsf(tgt[rs] - (float)gj));
                        s[na][2 * rs + c] = e; rsum += e;
                    }
            } else {
                #pragma unroll
                for (int na = 0; na < 8; na++)
                    #pragma unroll
                    for (int c = 0; c < 2; c++) {
                        const int gj = j0 + na * 8 + 2 * tg + c;
                        float e = (gj <= gi)
                            ? __expf(s[na][2 * rs + c] - slope * (float)(gi - gj))
                            : 0.f;
                        s[na][2 * rs + c] = e; rsum += e;
                    }
            }
            l2[rs] += rsum;
        }

        cp_wait<1>();       // V_jt done (K_next may pend)
        __syncthreads();

        // P -> sP as fp16 (warp-private rows)
        #pragma unroll
        for (int na = 0; na < 8; na++) {
            const int r = w * 16 + g, c = na * 8 + 2 * tg;
            *(__half2*)(sQP + r * VSTR + c * 2) =
                __floats2half2_rn(s[na][0], s[na][1]);
            *(__half2*)(sQP + (r + 8) * VSTR + c * 2) =
                __floats2half2_rn(s[na][2], s[na][3]);
        }
        __syncwarp();

        // GEMM2: O += P @ V (P via ldmatrix; V row-major via ldmatrix.trans)
        #pragma unroll
        for (int jc = 0; jc < 4; jc++) {
            uint32_t af[4];
            ldsm4(af, sQPa + pLane + jc * 32);
            uint32_t bf[4][4];
            #pragma unroll
            for (int n2 = 0; n2 < 4; n2++)
                ldsm4t(bf[n2], sVa + vLane + jc * 16 * VSTR + n2 * 32);
            #pragma unroll
            for (int na = 0; na < 8; na++)
                mma16(O[na], af, &bf[na >> 1][(na & 1) * 2]);
        }
    }

    // final l reduction (once)
    #pragma unroll
    for (int rs = 0; rs < 2; rs++) {
        l2[rs] += __shfl_xor_sync(0xffffffffu, l2[rs], 1);
        l2[rs] += __shfl_xor_sync(0xffffffffu, l2[rs], 2);
    }

    #pragma unroll
    for (int rs = 0; rs < 2; rs++) {
        const float inv = 1.0f / l2[rs];
        const size_t rowoff = (bS + i0 + w * 16 + g + 8 * rs) * DIMC + h * HDIM;
        #pragma unroll
        for (int na = 0; na < 8; na++)
            *(__half2*)&ao[rowoff + na * 8 + 2 * tg] =
                __floats2half2_rn(O[na][2 * rs] * inv, O[na][2 * rs + 1] * inv);
    }
}

// ============================================================
extern "C" void kernel_launch(void* const* d_in, const int* in_sizes, int n_in,
                              void* d_out, int out_size)
{
    const float* x   = (const float*)d_in[0];
    const float* gch = (const float*)d_in[1];
    const float* pch = (const float*)d_in[2];
    const float* wq  = (const float*)d_in[3];
    const float* wk  = (const float*)d_in[4];
    const float* wv  = (const float*)d_in[5];
    const float* wo  = (const float*)d_in[6];
    float* out = (float*)d_out;

    __half *qp, *kp, *vp, *aop, *xhp, *wtp;
    cudaGetSymbolAddress((void**)&qp,  g_q);
    cudaGetSymbolAddress((void**)&kp,  g_k);
    cudaGetSymbolAddress((void**)&vp,  g_v);
    cudaGetSymbolAddress((void**)&aop, g_ao);
    cudaGetSymbolAddress((void**)&xhp, g_xh);
    cudaGetSymbolAddress((void**)&wtp, g_wt);

    xcvt<<<(MROWS * DIMC) / (256 * 4), 256>>>(x, xhp);
    transpose_w<<<dim3(DIMC / 32, DIMC / 32, 4), dim3(32, 8)>>>(wq, wk, wv, wo, wtp);

    gemm_qkv3<<<dim3(DIMC / 128, MROWS / 128, 3), 256>>>(xhp, wtp, qp, kp, vp);

    attn_mma<<<dim3(SLEN / 64, NH, BATCH), 128>>>(qp, kp, vp, x, gch, aop);

    gemm_out<<<dim3(DIMC / 128, MROWS / 128), 256>>>(aop, wtp, out, x, gch, pch);
}